// round 2
// baseline (speedup 1.0000x reference)
#include <cuda_runtime.h>
#include <math.h>

#define Bn   512
#define Nn   199
#define NNp  200          // padded node count (row 199 zeroed)
#define Fn   64
#define Hn   4
#define Un   64
#define OUTC 455          // H*U + N
#define SROW 224          // per-warp staging row length (covers j = l + 32k, k<7)
#define KROW 224          // padded kernels row
#define NT   256
#define NW   8

// Scratch: transposed weighted adjacency AWt[h][m][n] = A[n][m] * params[h][n][m]
__device__ float g_AWt[Hn * Nn * Nn];

__global__ void prep_awt_kernel(const float* __restrict__ A,
                                const float* __restrict__ P) {
    int i = blockIdx.x * blockDim.x + threadIdx.x;
    if (i >= Hn * Nn * Nn) return;
    int h = i / (Nn * Nn);
    int rem = i - h * Nn * Nn;
    int m = rem / Nn;
    int n = rem - m * Nn;
    g_AWt[i] = A[n * Nn + m] * P[h * Nn * Nn + n * Nn + m];
}

__global__ __launch_bounds__(NT, 1)
void gc_kernel(const float* __restrict__ X, const float* __restrict__ A,
               const float* __restrict__ KER, const float* __restrict__ FC,
               const float* __restrict__ B1, const float* __restrict__ B2,
               float* __restrict__ out)
{
    extern __shared__ float sm[];
    float* Xs   = sm;                    // [NNp][Fn]
    float* Ys   = Xs + NNp * Fn;         // [NNp][Fn]  Y = X @ fc[h]
    float* Ks   = Ys + NNp * Fn;         // [Fn][KROW] kernels[h], zero padded
    float* fcs  = Ks + Fn * KROW;        // [Fn][Un]
    float* wbuf = fcs + Fn * Un;         // [NW][4][SROW] per-warp staging
    float* b1s  = wbuf + NW * 4 * SROW;  // [KROW]
    float* b2s  = b1s + KROW;            // [Un]

    const int b = blockIdx.x / Hn;
    const int h = blockIdx.x - b * Hn;
    const int tid = threadIdx.x;
    const int w = tid >> 5;
    const int l = tid & 31;

    // ---------------- load phase ----------------
    {
        const float4* xg = (const float4*)(X + (size_t)b * (Nn * Fn));
        float4* xs4 = (float4*)Xs;
        for (int i = tid; i < NNp * Fn / 4; i += NT)
            xs4[i] = (i < Nn * Fn / 4) ? xg[i] : make_float4(0.f, 0.f, 0.f, 0.f);

        const float* kg = KER + (size_t)h * (Fn * Nn);
        for (int i = tid; i < Fn * KROW; i += NT) {
            int f = i / KROW, j = i - f * KROW;
            Ks[i] = (j < Nn) ? kg[f * Nn + j] : 0.f;
        }
        const float4* fg = (const float4*)(FC + (size_t)h * (Fn * Un));
        float4* fcs4 = (float4*)fcs;
        for (int i = tid; i < Fn * Un / 4; i += NT) fcs4[i] = fg[i];

        for (int i = tid; i < KROW; i += NT) b1s[i] = (i < Nn) ? B1[h * Nn + i] : 0.f;
        if (tid < Un) b2s[tid] = B2[h * Un + tid];
    }
    __syncthreads();

    // ---------------- Ys = Xs @ fcs  (rows incl. zero pad row 199) ----------------
    for (int n0 = 4 * w; n0 < NNp; n0 += 4 * NW) {
        float2 a0 = make_float2(0.f, 0.f), a1 = a0, a2 = a0, a3 = a0;
        #pragma unroll 4
        for (int f4 = 0; f4 < Fn / 4; f4++) {
            float4 x0 = *(const float4*)&Xs[(n0 + 0) * Fn + 4 * f4];
            float4 x1 = *(const float4*)&Xs[(n0 + 1) * Fn + 4 * f4];
            float4 x2 = *(const float4*)&Xs[(n0 + 2) * Fn + 4 * f4];
            float4 x3 = *(const float4*)&Xs[(n0 + 3) * Fn + 4 * f4];
            float2 c0 = *(const float2*)&fcs[(4 * f4 + 0) * Un + 2 * l];
            float2 c1 = *(const float2*)&fcs[(4 * f4 + 1) * Un + 2 * l];
            float2 c2 = *(const float2*)&fcs[(4 * f4 + 2) * Un + 2 * l];
            float2 c3 = *(const float2*)&fcs[(4 * f4 + 3) * Un + 2 * l];
            a0.x += x0.x*c0.x + x0.y*c1.x + x0.z*c2.x + x0.w*c3.x;
            a0.y += x0.x*c0.y + x0.y*c1.y + x0.z*c2.y + x0.w*c3.y;
            a1.x += x1.x*c0.x + x1.y*c1.x + x1.z*c2.x + x1.w*c3.x;
            a1.y += x1.x*c0.y + x1.y*c1.y + x1.z*c2.y + x1.w*c3.y;
            a2.x += x2.x*c0.x + x2.y*c1.x + x2.z*c2.x + x2.w*c3.x;
            a2.y += x2.x*c0.y + x2.y*c1.y + x2.z*c2.y + x2.w*c3.y;
            a3.x += x3.x*c0.x + x3.y*c1.x + x3.z*c2.x + x3.w*c3.x;
            a3.y += x3.x*c0.y + x3.y*c1.y + x3.z*c2.y + x3.w*c3.y;
        }
        *(float2*)&Ys[(n0 + 0) * Fn + 2 * l] = a0;
        *(float2*)&Ys[(n0 + 1) * Fn + 2 * l] = a1;
        *(float2*)&Ys[(n0 + 2) * Fn + 2 * l] = a2;
        *(float2*)&Ys[(n0 + 3) * Fn + 2 * l] = a3;
    }
    __syncthreads();

    const float* AWh = g_AWt + (size_t)h * (Nn * Nn);
    float* wb = wbuf + w * (4 * SROW);

    // ---------------- main loop: 4 m-rows per warp ----------------
    for (int m0 = 4 * w; m0 < Nn; m0 += 4 * NW) {
        // stage AWt rows (zero padded)
        for (int i = l; i < 4 * SROW; i += 32) {
            int r = i / SROW, n = i - r * SROW;
            int m = m0 + r;
            wb[i] = (n < Nn && m < Nn) ? AWh[m * Nn + n] : 0.f;
        }
        __syncwarp();

        // feat[r][f(2l,2l+1)] = sum_n awt[r][n] * Xs[n][f]
        float2 f0 = make_float2(0.f, 0.f), f1 = f0, f2 = f0, f3 = f0;
        #pragma unroll 2
        for (int n4 = 0; n4 < NNp / 4; n4++) {
            float4 q0 = *(const float4*)&wb[0 * SROW + 4 * n4];
            float4 q1 = *(const float4*)&wb[1 * SROW + 4 * n4];
            float4 q2 = *(const float4*)&wb[2 * SROW + 4 * n4];
            float4 q3 = *(const float4*)&wb[3 * SROW + 4 * n4];
            float A0[4] = {q0.x, q0.y, q0.z, q0.w};
            float A1[4] = {q1.x, q1.y, q1.z, q1.w};
            float A2[4] = {q2.x, q2.y, q2.z, q2.w};
            float A3[4] = {q3.x, q3.y, q3.z, q3.w};
            #pragma unroll
            for (int jj = 0; jj < 4; jj++) {
                float2 x = *(const float2*)&Xs[(4 * n4 + jj) * Fn + 2 * l];
                f0.x += A0[jj] * x.x; f0.y += A0[jj] * x.y;
                f1.x += A1[jj] * x.x; f1.y += A1[jj] * x.y;
                f2.x += A2[jj] * x.x; f2.y += A2[jj] * x.y;
                f3.x += A3[jj] * x.x; f3.y += A3[jj] * x.y;
            }
        }
        __syncwarp();
        *(float2*)&wb[0 * SROW + 2 * l] = f0;
        *(float2*)&wb[1 * SROW + 2 * l] = f1;
        *(float2*)&wb[2 * SROW + 2 * l] = f2;
        *(float2*)&wb[3 * SROW + 2 * l] = f3;
        __syncwarp();

        // dense[r][j(l+32k)] = sum_f feat[r][f] * Ks[f][j] + b1[j]
        float dens[4][7];
        #pragma unroll
        for (int r = 0; r < 4; r++)
            #pragma unroll
            for (int k = 0; k < 7; k++) dens[r][k] = b1s[l + 32 * k];
        #pragma unroll 2
        for (int f4 = 0; f4 < Fn / 4; f4++) {
            float4 q0 = *(const float4*)&wb[0 * SROW + 4 * f4];
            float4 q1 = *(const float4*)&wb[1 * SROW + 4 * f4];
            float4 q2 = *(const float4*)&wb[2 * SROW + 4 * f4];
            float4 q3 = *(const float4*)&wb[3 * SROW + 4 * f4];
            float F0[4] = {q0.x, q0.y, q0.z, q0.w};
            float F1[4] = {q1.x, q1.y, q1.z, q1.w};
            float F2[4] = {q2.x, q2.y, q2.z, q2.w};
            float F3[4] = {q3.x, q3.y, q3.z, q3.w};
            #pragma unroll
            for (int jj = 0; jj < 4; jj++) {
                int f = 4 * f4 + jj;
                float ks[7];
                #pragma unroll
                for (int k = 0; k < 7; k++) ks[k] = Ks[f * KROW + l + 32 * k];
                #pragma unroll
                for (int k = 0; k < 7; k++) {
                    dens[0][k] += F0[jj] * ks[k];
                    dens[1][k] += F1[jj] * ks[k];
                    dens[2][k] += F2[jj] * ks[k];
                    dens[3][k] += F3[jj] * ks[k];
                }
            }
        }
        __syncwarp();

        // adjacency-masked softmax (exact: exp(-1e16) == 0 in fp32)
        #pragma unroll
        for (int r = 0; r < 4; r++) {
            int m = m0 + r;
            if (m < Nn) {
                float av[7];
                #pragma unroll
                for (int k = 0; k < 7; k++) {
                    int j = l + 32 * k;
                    av[k] = (j < Nn) ? A[m * Nn + j] : 0.f;
                }
                float mx = -3.0e38f;
                #pragma unroll
                for (int k = 0; k < 7; k++)
                    if (av[k] != 0.f) mx = fmaxf(mx, dens[r][k]);
                #pragma unroll
                for (int o = 16; o > 0; o >>= 1)
                    mx = fmaxf(mx, __shfl_xor_sync(0xffffffffu, mx, o));
                float s = 0.f;
                #pragma unroll
                for (int k = 0; k < 7; k++) {
                    float e = (av[k] != 0.f) ? __expf(dens[r][k] - mx) : 0.f;
                    av[k] = e; s += e;
                }
                #pragma unroll
                for (int o = 16; o > 0; o >>= 1)
                    s += __shfl_xor_sync(0xffffffffu, s, o);
                float inv = 1.f / s;
                size_t mrow = ((size_t)b * Nn + m) * OUTC;
                #pragma unroll
                for (int k = 0; k < 7; k++) {
                    int j = l + 32 * k;
                    float p = av[k] * inv;
                    wb[r * SROW + j] = p;                       // j < 224 always
                    if (h == Hn - 1 && j < Nn)
                        out[mrow + Hn * Un + j] = p;            // last-head mask
                }
            }
        }
        __syncwarp();

        // out[r][u(2l,2l+1)] = sum_j mask[r][j] * Ys[j][u] + b2[u]
        float2 o0 = make_float2(b2s[2 * l], b2s[2 * l + 1]);
        float2 o1 = o0, o2 = o0, o3 = o0;
        #pragma unroll 2
        for (int j4 = 0; j4 < NNp / 4; j4++) {
            float4 q0 = *(const float4*)&wb[0 * SROW + 4 * j4];
            float4 q1 = *(const float4*)&wb[1 * SROW + 4 * j4];
            float4 q2 = *(const float4*)&wb[2 * SROW + 4 * j4];
            float4 q3 = *(const float4*)&wb[3 * SROW + 4 * j4];
            float P0[4] = {q0.x, q0.y, q0.z, q0.w};
            float P1[4] = {q1.x, q1.y, q1.z, q1.w};
            float P2[4] = {q2.x, q2.y, q2.z, q2.w};
            float P3[4] = {q3.x, q3.y, q3.z, q3.w};
            #pragma unroll
            for (int jj = 0; jj < 4; jj++) {
                float2 y = *(const float2*)&Ys[(4 * j4 + jj) * Fn + 2 * l];
                o0.x += P0[jj] * y.x; o0.y += P0[jj] * y.y;
                o1.x += P1[jj] * y.x; o1.y += P1[jj] * y.y;
                o2.x += P2[jj] * y.x; o2.y += P2[jj] * y.y;
                o3.x += P3[jj] * y.x; o3.y += P3[jj] * y.y;
            }
        }
        #pragma unroll
        for (int r = 0; r < 4; r++) {
            int m = m0 + r;
            if (m < Nn) {
                size_t base = ((size_t)b * Nn + m) * OUTC + h * Un + 2 * l;
                float2 ov = (r == 0) ? o0 : (r == 1) ? o1 : (r == 2) ? o2 : o3;
                out[base] = ov.x;
                out[base + 1] = ov.y;
            }
        }
        __syncwarp();
    }
}

static const size_t SMEM_BYTES =
    (size_t)(NNp * Fn + NNp * Fn + Fn * KROW + Fn * Un + NW * 4 * SROW + KROW + Un) * 4;

extern "C" void kernel_launch(void* const* d_in, const int* in_sizes, int n_in,
                              void* d_out, int out_size) {
    const float* X   = (const float*)d_in[0];
    const float* A   = (const float*)d_in[1];
    const float* KER = (const float*)d_in[2];
    const float* P   = (const float*)d_in[3];
    const float* FC  = (const float*)d_in[4];
    const float* B1  = (const float*)d_in[5];
    const float* B2  = (const float*)d_in[6];
    float* out = (float*)d_out;

    cudaFuncSetAttribute(gc_kernel, cudaFuncAttributeMaxDynamicSharedMemorySize,
                         (int)SMEM_BYTES);

    prep_awt_kernel<<<(Hn * Nn * Nn + 255) / 256, 256>>>(A, P);
    gc_kernel<<<Bn * Hn, NT, SMEM_BYTES>>>(X, A, KER, FC, B1, B2, out);
}

// round 3
// speedup vs baseline: 1.1866x; 1.1866x over previous
#include <cuda_runtime.h>
#include <math.h>

#define Bn   512
#define Nn   199
#define NNp  200          // padded node count (row 199 zeroed)
#define Fn   64
#define Hn   4
#define Un   64
#define OUTC 455          // H*U + N
#define SROW 224          // per-warp staging row length (covers j = l + 32k, k<7)
#define KROW 224          // padded kernels row
#define NT   512
#define NW   16

// Scratch: transposed weighted adjacency AWt[h][m][n] = A[n][m] * params[h][n][m]
__device__ float g_AWt[Hn * Nn * Nn];

__global__ void prep_awt_kernel(const float* __restrict__ A,
                                const float* __restrict__ P) {
    int i = blockIdx.x * blockDim.x + threadIdx.x;
    if (i >= Hn * Nn * Nn) return;
    int h = i / (Nn * Nn);
    int rem = i - h * Nn * Nn;
    int m = rem / Nn;
    int n = rem - m * Nn;
    g_AWt[i] = A[n * Nn + m] * P[h * Nn * Nn + n * Nn + m];
}

__global__ __launch_bounds__(NT, 1)
void gc_kernel(const float* __restrict__ X, const float* __restrict__ A,
               const float* __restrict__ KER, const float* __restrict__ FC,
               const float* __restrict__ B1, const float* __restrict__ B2,
               float* __restrict__ out)
{
    extern __shared__ float sm[];
    float* Xs   = sm;                    // [NNp][Fn]
    float* Ys   = Xs + NNp * Fn;         // [NNp][Fn]  Y = X @ fc[h]
    float* Ks   = Ys + NNp * Fn;         // [Fn][KROW] kernels[h], zero padded
    float* wbuf = Ks + Fn * KROW;        // [NW][4][SROW] per-warp staging
    float* fcs  = wbuf;                  // [Fn][Un] ALIAS: used only before main loop
    float* b1s  = wbuf + NW * 4 * SROW;  // [KROW]
    float* b2s  = b1s + KROW;            // [Un]

    const int b = blockIdx.x / Hn;
    const int h = blockIdx.x - b * Hn;
    const int tid = threadIdx.x;
    const int w = tid >> 5;
    const int l = tid & 31;

    // ---------------- load phase ----------------
    {
        const float4* xg = (const float4*)(X + (size_t)b * (Nn * Fn));
        float4* xs4 = (float4*)Xs;
        for (int i = tid; i < NNp * Fn / 4; i += NT)
            xs4[i] = (i < Nn * Fn / 4) ? xg[i] : make_float4(0.f, 0.f, 0.f, 0.f);

        const float* kg = KER + (size_t)h * (Fn * Nn);
        for (int i = tid; i < Fn * KROW; i += NT) {
            int f = i / KROW, j = i - f * KROW;
            Ks[i] = (j < Nn) ? kg[f * Nn + j] : 0.f;
        }
        const float4* fg = (const float4*)(FC + (size_t)h * (Fn * Un));
        float4* fcs4 = (float4*)fcs;
        for (int i = tid; i < Fn * Un / 4; i += NT) fcs4[i] = fg[i];

        for (int i = tid; i < KROW; i += NT) b1s[i] = (i < Nn) ? B1[h * Nn + i] : 0.f;
        if (tid < Un) b2s[tid] = B2[h * Un + tid];
    }
    __syncthreads();

    // ---------------- Ys = Xs @ fcs  (rows incl. zero pad row 199) ----------------
    for (int n0 = 4 * w; n0 < NNp; n0 += 4 * NW) {
        float2 a0 = make_float2(0.f, 0.f), a1 = a0, a2 = a0, a3 = a0;
        #pragma unroll 4
        for (int f4 = 0; f4 < Fn / 4; f4++) {
            float4 x0 = *(const float4*)&Xs[(n0 + 0) * Fn + 4 * f4];
            float4 x1 = *(const float4*)&Xs[(n0 + 1) * Fn + 4 * f4];
            float4 x2 = *(const float4*)&Xs[(n0 + 2) * Fn + 4 * f4];
            float4 x3 = *(const float4*)&Xs[(n0 + 3) * Fn + 4 * f4];
            float2 c0 = *(const float2*)&fcs[(4 * f4 + 0) * Un + 2 * l];
            float2 c1 = *(const float2*)&fcs[(4 * f4 + 1) * Un + 2 * l];
            float2 c2 = *(const float2*)&fcs[(4 * f4 + 2) * Un + 2 * l];
            float2 c3 = *(const float2*)&fcs[(4 * f4 + 3) * Un + 2 * l];
            a0.x += x0.x*c0.x + x0.y*c1.x + x0.z*c2.x + x0.w*c3.x;
            a0.y += x0.x*c0.y + x0.y*c1.y + x0.z*c2.y + x0.w*c3.y;
            a1.x += x1.x*c0.x + x1.y*c1.x + x1.z*c2.x + x1.w*c3.x;
            a1.y += x1.x*c0.y + x1.y*c1.y + x1.z*c2.y + x1.w*c3.y;
            a2.x += x2.x*c0.x + x2.y*c1.x + x2.z*c2.x + x2.w*c3.x;
            a2.y += x2.x*c0.y + x2.y*c1.y + x2.z*c2.y + x2.w*c3.y;
            a3.x += x3.x*c0.x + x3.y*c1.x + x3.z*c2.x + x3.w*c3.x;
            a3.y += x3.x*c0.y + x3.y*c1.y + x3.z*c2.y + x3.w*c3.y;
        }
        *(float2*)&Ys[(n0 + 0) * Fn + 2 * l] = a0;
        *(float2*)&Ys[(n0 + 1) * Fn + 2 * l] = a1;
        *(float2*)&Ys[(n0 + 2) * Fn + 2 * l] = a2;
        *(float2*)&Ys[(n0 + 3) * Fn + 2 * l] = a3;
    }
    __syncthreads();

    const float* AWh = g_AWt + (size_t)h * (Nn * Nn);
    float* wb = wbuf + w * (4 * SROW);

    // ---------------- main loop: 4 m-rows per warp ----------------
    for (int m0 = 4 * w; m0 < Nn; m0 += 4 * NW) {
        // stage AWt rows (zero padded)
        for (int i = l; i < 4 * SROW; i += 32) {
            int r = i / SROW, n = i - r * SROW;
            int m = m0 + r;
            wb[i] = (n < Nn && m < Nn) ? AWh[m * Nn + n] : 0.f;
        }
        __syncwarp();

        // feat[r][f(2l,2l+1)] = sum_n awt[r][n] * Xs[n][f]
        float2 f0 = make_float2(0.f, 0.f), f1 = f0, f2 = f0, f3 = f0;
        #pragma unroll 2
        for (int n4 = 0; n4 < NNp / 4; n4++) {
            float4 q0 = *(const float4*)&wb[0 * SROW + 4 * n4];
            float4 q1 = *(const float4*)&wb[1 * SROW + 4 * n4];
            float4 q2 = *(const float4*)&wb[2 * SROW + 4 * n4];
            float4 q3 = *(const float4*)&wb[3 * SROW + 4 * n4];
            float A0[4] = {q0.x, q0.y, q0.z, q0.w};
            float A1[4] = {q1.x, q1.y, q1.z, q1.w};
            float A2[4] = {q2.x, q2.y, q2.z, q2.w};
            float A3[4] = {q3.x, q3.y, q3.z, q3.w};
            #pragma unroll
            for (int jj = 0; jj < 4; jj++) {
                float2 x = *(const float2*)&Xs[(4 * n4 + jj) * Fn + 2 * l];
                f0.x += A0[jj] * x.x; f0.y += A0[jj] * x.y;
                f1.x += A1[jj] * x.x; f1.y += A1[jj] * x.y;
                f2.x += A2[jj] * x.x; f2.y += A2[jj] * x.y;
                f3.x += A3[jj] * x.x; f3.y += A3[jj] * x.y;
            }
        }
        __syncwarp();
        *(float2*)&wb[0 * SROW + 2 * l] = f0;
        *(float2*)&wb[1 * SROW + 2 * l] = f1;
        *(float2*)&wb[2 * SROW + 2 * l] = f2;
        *(float2*)&wb[3 * SROW + 2 * l] = f3;
        __syncwarp();

        // dense[r][j(l+32k)] = sum_f feat[r][f] * Ks[f][j] + b1[j]
        float dens[4][7];
        #pragma unroll
        for (int r = 0; r < 4; r++)
            #pragma unroll
            for (int k = 0; k < 7; k++) dens[r][k] = b1s[l + 32 * k];
        #pragma unroll 2
        for (int f4 = 0; f4 < Fn / 4; f4++) {
            float4 q0 = *(const float4*)&wb[0 * SROW + 4 * f4];
            float4 q1 = *(const float4*)&wb[1 * SROW + 4 * f4];
            float4 q2 = *(const float4*)&wb[2 * SROW + 4 * f4];
            float4 q3 = *(const float4*)&wb[3 * SROW + 4 * f4];
            float F0[4] = {q0.x, q0.y, q0.z, q0.w};
            float F1[4] = {q1.x, q1.y, q1.z, q1.w};
            float F2[4] = {q2.x, q2.y, q2.z, q2.w};
            float F3[4] = {q3.x, q3.y, q3.z, q3.w};
            #pragma unroll
            for (int jj = 0; jj < 4; jj++) {
                int f = 4 * f4 + jj;
                float ks[7];
                #pragma unroll
                for (int k = 0; k < 7; k++) ks[k] = Ks[f * KROW + l + 32 * k];
                #pragma unroll
                for (int k = 0; k < 7; k++) {
                    dens[0][k] += F0[jj] * ks[k];
                    dens[1][k] += F1[jj] * ks[k];
                    dens[2][k] += F2[jj] * ks[k];
                    dens[3][k] += F3[jj] * ks[k];
                }
            }
        }
        __syncwarp();

        // adjacency-masked softmax (exact: exp(-1e16) == 0 in fp32)
        #pragma unroll
        for (int r = 0; r < 4; r++) {
            int m = m0 + r;
            if (m < Nn) {
                float av[7];
                #pragma unroll
                for (int k = 0; k < 7; k++) {
                    int j = l + 32 * k;
                    av[k] = (j < Nn) ? A[m * Nn + j] : 0.f;
                }
                float mx = -3.0e38f;
                #pragma unroll
                for (int k = 0; k < 7; k++)
                    if (av[k] != 0.f) mx = fmaxf(mx, dens[r][k]);
                #pragma unroll
                for (int o = 16; o > 0; o >>= 1)
                    mx = fmaxf(mx, __shfl_xor_sync(0xffffffffu, mx, o));
                float s = 0.f;
                #pragma unroll
                for (int k = 0; k < 7; k++) {
                    float e = (av[k] != 0.f) ? __expf(dens[r][k] - mx) : 0.f;
                    av[k] = e; s += e;
                }
                #pragma unroll
                for (int o = 16; o > 0; o >>= 1)
                    s += __shfl_xor_sync(0xffffffffu, s, o);
                float inv = 1.f / s;
                size_t mrow = ((size_t)b * Nn + m) * OUTC;
                #pragma unroll
                for (int k = 0; k < 7; k++) {
                    int j = l + 32 * k;
                    float p = av[k] * inv;
                    wb[r * SROW + j] = p;                       // j < 224 always
                    if (h == Hn - 1 && j < Nn)
                        out[mrow + Hn * Un + j] = p;            // last-head mask
                }
            }
        }
        __syncwarp();

        // out[r][u(2l,2l+1)] = sum_j mask[r][j] * Ys[j][u] + b2[u]
        float2 o0 = make_float2(b2s[2 * l], b2s[2 * l + 1]);
        float2 o1 = o0, o2 = o0, o3 = o0;
        #pragma unroll 2
        for (int j4 = 0; j4 < NNp / 4; j4++) {
            float4 q0 = *(const float4*)&wb[0 * SROW + 4 * j4];
            float4 q1 = *(const float4*)&wb[1 * SROW + 4 * j4];
            float4 q2 = *(const float4*)&wb[2 * SROW + 4 * j4];
            float4 q3 = *(const float4*)&wb[3 * SROW + 4 * j4];
            float P0[4] = {q0.x, q0.y, q0.z, q0.w};
            float P1[4] = {q1.x, q1.y, q1.z, q1.w};
            float P2[4] = {q2.x, q2.y, q2.z, q2.w};
            float P3[4] = {q3.x, q3.y, q3.z, q3.w};
            #pragma unroll
            for (int jj = 0; jj < 4; jj++) {
                float2 y = *(const float2*)&Ys[(4 * j4 + jj) * Fn + 2 * l];
                o0.x += P0[jj] * y.x; o0.y += P0[jj] * y.y;
                o1.x += P1[jj] * y.x; o1.y += P1[jj] * y.y;
                o2.x += P2[jj] * y.x; o2.y += P2[jj] * y.y;
                o3.x += P3[jj] * y.x; o3.y += P3[jj] * y.y;
            }
        }
        #pragma unroll
        for (int r = 0; r < 4; r++) {
            int m = m0 + r;
            if (m < Nn) {
                size_t base = ((size_t)b * Nn + m) * OUTC + h * Un + 2 * l;
                float2 ov = (r == 0) ? o0 : (r == 1) ? o1 : (r == 2) ? o2 : o3;
                out[base] = ov.x;
                out[base + 1] = ov.y;
            }
        }
        __syncwarp();
    }
}

static const size_t SMEM_BYTES =
    (size_t)(NNp * Fn + NNp * Fn + Fn * KROW + NW * 4 * SROW + KROW + Un) * 4;

extern "C" void kernel_launch(void* const* d_in, const int* in_sizes, int n_in,
                              void* d_out, int out_size) {
    const float* X   = (const float*)d_in[0];
    const float* A   = (const float*)d_in[1];
    const float* KER = (const float*)d_in[2];
    const float* P   = (const float*)d_in[3];
    const float* FC  = (const float*)d_in[4];
    const float* B1  = (const float*)d_in[5];
    const float* B2  = (const float*)d_in[6];
    float* out = (float*)d_out;

    cudaFuncSetAttribute(gc_kernel, cudaFuncAttributeMaxDynamicSharedMemorySize,
                         (int)SMEM_BYTES);

    prep_awt_kernel<<<(Hn * Nn * Nn + 255) / 256, 256>>>(A, P);
    gc_kernel<<<Bn * Hn, NT, SMEM_BYTES>>>(X, A, KER, FC, B1, B2, out);
}

// round 4
// speedup vs baseline: 1.4588x; 1.2294x over previous
#include <cuda_runtime.h>
#include <math.h>

#define Bn   512
#define Nn   199
#define NP   200          // padded nodes
#define Fn   64
#define Hn   4
#define Un   64
#define OUTC 455          // H*U + N
#define KROW 224          // padded kernels row (j = l + 32k, k<7)
#define NT   512
#define NW   16

typedef unsigned long long u64;

// weighted adjacency, transposed+padded: g_G[h][n][m] = A[n,m]*P[h,n,m], zero pad
__device__ float g_G[Hn * NP * NP];

__device__ __forceinline__ u64 fma2(u64 a, u64 b, u64 c) {
    u64 d; asm("fma.rn.f32x2 %0, %1, %2, %3;" : "=l"(d) : "l"(a), "l"(b), "l"(c));
    return d;
}
__device__ __forceinline__ u64 pack2(float lo, float hi) {
    u64 d; asm("mov.b64 %0, {%1, %2};" : "=l"(d) : "f"(lo), "f"(hi)); return d;
}
__device__ __forceinline__ float2 unpack2(u64 v) {
    float2 r; asm("mov.b64 {%0, %1}, %2;" : "=f"(r.x), "=f"(r.y) : "l"(v)); return r;
}

__global__ void prep_g(const float* __restrict__ A, const float* __restrict__ P) {
    int i = blockIdx.x * blockDim.x + threadIdx.x;
    if (i >= Hn * NP * NP) return;
    int h = i / (NP * NP);
    int rem = i - h * NP * NP;
    int n = rem / NP;
    int m = rem - n * NP;
    float v = 0.f;
    if (n < Nn && m < Nn) v = A[n * Nn + m] * P[(h * Nn + n) * Nn + m];
    g_G[i] = v;
}

// One chunk of 2*PAIRS m-rows, fully per-warp. wb: [224][2*PAIRS] staging.
template<int PAIRS>
__device__ __forceinline__ void do_chunk(
    int m0, int b, int h, int l, bool last_h,
    const float* __restrict__ Xs, const float* __restrict__ Ks,
    const float* __restrict__ fcs, const float* __restrict__ b1s,
    const float* __restrict__ b2s, float* __restrict__ wb,
    const float* __restrict__ A, float* __restrict__ out)
{
    const int RS = 2 * PAIRS;

    // ---- feat[r][f] = sum_n G[n][r] * X[n][f]  (row-pair packed over f=2l,2l+1)
    u64 aX[PAIRS], aY[PAIRS];
    #pragma unroll
    for (int p = 0; p < PAIRS; p++) { aX[p] = 0ull; aY[p] = 0ull; }
    const float* Gh = g_G + (size_t)h * NP * NP + m0;
    #pragma unroll 4
    for (int n = 0; n < NP; n++) {
        float2 x = *(const float2*)&Xs[n * Fn + 2 * l];
        u64 xx = pack2(x.x, x.x), xy = pack2(x.y, x.y);
        const u64* gp = (const u64*)(Gh + (size_t)n * NP);
        #pragma unroll
        for (int p = 0; p < PAIRS; p++) {
            u64 g = gp[p];                        // (G[n][m0+2p], G[n][m0+2p+1])
            aX[p] = fma2(g, xx, aX[p]);
            aY[p] = fma2(g, xy, aY[p]);
        }
    }
    __syncwarp();      // prior chunk's wb reads done before restaging
    #pragma unroll
    for (int p = 0; p < PAIRS; p++) {
        *(u64*)&wb[(2 * l) * RS + 2 * p]     = aX[p];
        *(u64*)&wb[(2 * l + 1) * RS + 2 * p] = aY[p];
    }
    __syncwarp();

    // ---- dense[r][j] = sum_f feat[r][f]*K[f][j] + b1[j], j = l+32k
    u64 dP[PAIRS][7];
    #pragma unroll
    for (int k = 0; k < 7; k++) {
        float bv = b1s[l + 32 * k];
        u64 bb = pack2(bv, bv);
        #pragma unroll
        for (int p = 0; p < PAIRS; p++) dP[p][k] = bb;
    }
    #pragma unroll 2
    for (int f = 0; f < Fn; f++) {
        u64 fp[PAIRS];
        #pragma unroll
        for (int p = 0; p < PAIRS; p++) fp[p] = *(const u64*)&wb[f * RS + 2 * p];
        #pragma unroll
        for (int k = 0; k < 7; k++) {
            float kv = Ks[f * KROW + l + 32 * k];
            u64 kk = pack2(kv, kv);
            #pragma unroll
            for (int p = 0; p < PAIRS; p++) dP[p][k] = fma2(fp[p], kk, dP[p][k]);
        }
    }
    __syncwarp();      // all wb(feat) reads done before mask overwrites

    // ---- adjacency-masked softmax per row
    #pragma unroll
    for (int p = 0; p < PAIRS; p++) {
        float2 dk[7];
        #pragma unroll
        for (int k = 0; k < 7; k++) dk[k] = unpack2(dP[p][k]);
        #pragma unroll
        for (int s = 0; s < 2; s++) {
            int r = 2 * p + s, m = m0 + r;
            if (m < Nn) {
                float dv[7], av[7];
                #pragma unroll
                for (int k = 0; k < 7; k++) dv[k] = s ? dk[k].y : dk[k].x;
                #pragma unroll
                for (int k = 0; k < 7; k++) {
                    int j = l + 32 * k;
                    av[k] = (j < Nn) ? A[m * Nn + j] : 0.f;
                }
                float mx = -3.0e38f;
                #pragma unroll
                for (int k = 0; k < 7; k++) if (av[k] != 0.f) mx = fmaxf(mx, dv[k]);
                #pragma unroll
                for (int o = 16; o > 0; o >>= 1)
                    mx = fmaxf(mx, __shfl_xor_sync(0xffffffffu, mx, o));
                float ssum = 0.f;
                #pragma unroll
                for (int k = 0; k < 7; k++) {
                    float e = (av[k] != 0.f) ? __expf(dv[k] - mx) : 0.f;
                    av[k] = e; ssum += e;
                }
                #pragma unroll
                for (int o = 16; o > 0; o >>= 1)
                    ssum += __shfl_xor_sync(0xffffffffu, ssum, o);
                float inv = 1.f / ssum;
                size_t mrow = ((size_t)b * Nn + m) * OUTC + Hn * Un;
                #pragma unroll
                for (int k = 0; k < 7; k++) {
                    int j = l + 32 * k;
                    float pv = av[k] * inv;
                    wb[j * RS + r] = pv;
                    if (last_h && j < Nn) out[mrow + j] = pv;
                }
            } else {
                #pragma unroll
                for (int k = 0; k < 7; k++) wb[(l + 32 * k) * RS + r] = 0.f;
            }
        }
    }
    __syncwarp();

    // ---- node[r][f] = sum_j mask[r][j] * X[j][f]  (row-pair packed)
    u64 nX[PAIRS], nY[PAIRS];
    #pragma unroll
    for (int p = 0; p < PAIRS; p++) { nX[p] = 0ull; nY[p] = 0ull; }
    #pragma unroll 4
    for (int j = 0; j < NP; j++) {
        float2 x = *(const float2*)&Xs[j * Fn + 2 * l];
        u64 xx = pack2(x.x, x.x), xy = pack2(x.y, x.y);
        #pragma unroll
        for (int p = 0; p < PAIRS; p++) {
            u64 mm = *(const u64*)&wb[j * RS + 2 * p];
            nX[p] = fma2(mm, xx, nX[p]);
            nY[p] = fma2(mm, xy, nY[p]);
        }
    }
    __syncwarp();      // mask reads done before node staging overwrites
    #pragma unroll
    for (int p = 0; p < PAIRS; p++) {
        *(u64*)&wb[(2 * l) * RS + 2 * p]     = nX[p];
        *(u64*)&wb[(2 * l + 1) * RS + 2 * p] = nY[p];
    }
    __syncwarp();

    // ---- out[r][u] = sum_f node[r][f] * fc[f][u] + b2[u]
    u64 oX[PAIRS], oY[PAIRS];
    {
        u64 bx = pack2(b2s[2 * l], b2s[2 * l]);
        u64 by = pack2(b2s[2 * l + 1], b2s[2 * l + 1]);
        #pragma unroll
        for (int p = 0; p < PAIRS; p++) { oX[p] = bx; oY[p] = by; }
    }
    #pragma unroll 2
    for (int f = 0; f < Fn; f++) {
        float2 c = *(const float2*)&fcs[f * Un + 2 * l];
        u64 cx = pack2(c.x, c.x), cy = pack2(c.y, c.y);
        #pragma unroll
        for (int p = 0; p < PAIRS; p++) {
            u64 nn = *(const u64*)&wb[f * RS + 2 * p];
            oX[p] = fma2(nn, cx, oX[p]);
            oY[p] = fma2(nn, cy, oY[p]);
        }
    }
    #pragma unroll
    for (int p = 0; p < PAIRS; p++) {
        float2 vx = unpack2(oX[p]);   // rows (2p, 2p+1) at u = 2l
        float2 vy = unpack2(oY[p]);   // rows (2p, 2p+1) at u = 2l+1
        int m = m0 + 2 * p;
        if (m < Nn) {
            float* o = out + ((size_t)b * Nn + m) * OUTC + h * Un;
            o[2 * l] = vx.x; o[2 * l + 1] = vy.x;
        }
        if (m + 1 < Nn) {
            float* o = out + ((size_t)b * Nn + m + 1) * OUTC + h * Un;
            o[2 * l] = vx.y; o[2 * l + 1] = vy.y;
        }
    }
    __syncwarp();
}

// smem: Xs 12800 | Ks 14336 | fcs 4096 | wbuf 23296 | b1s 224 | b2s 64  = 219,264 B
#define WBUF_FLOATS (4 * (KROW * 8) + 12 * (KROW * 6))

__global__ __launch_bounds__(NT, 1)
void gc_kernel(const float* __restrict__ X, const float* __restrict__ A,
               const float* __restrict__ KER, const float* __restrict__ FC,
               const float* __restrict__ B1, const float* __restrict__ B2,
               float* __restrict__ out)
{
    extern __shared__ float sm[];
    float* Xs   = sm;                      // [NP][Fn]
    float* Ks   = Xs + NP * Fn;            // [Fn][KROW]
    float* fcs  = Ks + Fn * KROW;          // [Fn][Un]
    float* wbuf = fcs + Fn * Un;           // per-warp staging
    float* b1s  = wbuf + WBUF_FLOATS;      // [KROW]
    float* b2s  = b1s + KROW;              // [Un]

    const int b = blockIdx.x / Hn;
    const int h = blockIdx.x - b * Hn;
    const int tid = threadIdx.x;
    const int w = tid >> 5;
    const int l = tid & 31;
    const bool last_h = (h == Hn - 1);

    // ---------------- load phase ----------------
    {
        const float4* xg = (const float4*)(X + (size_t)b * (Nn * Fn));
        float4* xs4 = (float4*)Xs;
        for (int i = tid; i < NP * Fn / 4; i += NT)
            xs4[i] = (i < Nn * Fn / 4) ? xg[i] : make_float4(0.f, 0.f, 0.f, 0.f);

        const float* kg = KER + (size_t)h * (Fn * Nn);
        for (int i = tid; i < Fn * KROW; i += NT) {
            int f = i / KROW, j = i - f * KROW;
            Ks[i] = (j < Nn) ? kg[f * Nn + j] : 0.f;
        }
        const float4* fg = (const float4*)(FC + (size_t)h * (Fn * Un));
        float4* fcs4 = (float4*)fcs;
        for (int i = tid; i < Fn * Un / 4; i += NT) fcs4[i] = fg[i];

        for (int i = tid; i < KROW; i += NT) b1s[i] = (i < Nn) ? B1[h * Nn + i] : 0.f;
        if (tid < Un) b2s[tid] = B2[h * Un + tid];
    }
    __syncthreads();

    // per-warp staging base: warps 0-3 get [224][8], warps 4-15 get [224][6]
    float* wb = wbuf + (w < 4 ? w * (KROW * 8)
                              : 4 * (KROW * 8) + (w - 4) * (KROW * 6));

    // schedule: 200 rows = 4x(8-row chunk) + 28x(6-row chunk); 12% max imbalance
    if (w < 4) {
        do_chunk<4>(8 * w,          b, h, l, last_h, Xs, Ks, fcs, b1s, b2s, wb, A, out);
        do_chunk<3>(32 + 6 * w,     b, h, l, last_h, Xs, Ks, fcs, b1s, b2s, wb, A, out);
    } else {
        int c0 = 4 + 2 * (w - 4);
        do_chunk<3>(32 + 6 * c0,       b, h, l, last_h, Xs, Ks, fcs, b1s, b2s, wb, A, out);
        do_chunk<3>(32 + 6 * (c0 + 1), b, h, l, last_h, Xs, Ks, fcs, b1s, b2s, wb, A, out);
    }
}

static const size_t SMEM_BYTES =
    (size_t)(NP * Fn + Fn * KROW + Fn * Un + WBUF_FLOATS + KROW + Un) * 4;

extern "C" void kernel_launch(void* const* d_in, const int* in_sizes, int n_in,
                              void* d_out, int out_size) {
    const float* X   = (const float*)d_in[0];
    const float* A   = (const float*)d_in[1];
    const float* KER = (const float*)d_in[2];
    const float* P   = (const float*)d_in[3];
    const float* FC  = (const float*)d_in[4];
    const float* B1  = (const float*)d_in[5];
    const float* B2  = (const float*)d_in[6];
    float* out = (float*)d_out;

    cudaFuncSetAttribute(gc_kernel, cudaFuncAttributeMaxDynamicSharedMemorySize,
                         (int)SMEM_BYTES);

    prep_g<<<(Hn * NP * NP + 255) / 256, 256>>>(A, P);
    gc_kernel<<<Bn * Hn, NT, SMEM_BYTES>>>(X, A, KER, FC, B1, B2, out);
}

// round 5
// speedup vs baseline: 1.4609x; 1.0014x over previous
#include <cuda_runtime.h>
#include <math.h>

#define Bn   512
#define Nn   199
#define NP   200          // padded nodes
#define Fn   64
#define Hn   4
#define Un   64
#define OUTC 455          // H*U + N
#define KROW 224          // padded kernels row (j = l + 32k, k<7)
#define NT   512
#define NW   16

typedef unsigned long long u64;

// weighted adjacency, transposed+padded: g_G[h][n][m] = A[n,m]*P[h,n,m], zero pad
__device__ float g_G[Hn * NP * NP];

__device__ __forceinline__ u64 fma2(u64 a, u64 b, u64 c) {
    u64 d; asm("fma.rn.f32x2 %0, %1, %2, %3;" : "=l"(d) : "l"(a), "l"(b), "l"(c));
    return d;
}
__device__ __forceinline__ u64 pack2(float lo, float hi) {
    u64 d; asm("mov.b64 %0, {%1, %2};" : "=l"(d) : "f"(lo), "f"(hi)); return d;
}
__device__ __forceinline__ float2 unpack2(u64 v) {
    float2 r; asm("mov.b64 {%0, %1}, %2;" : "=f"(r.x), "=f"(r.y) : "l"(v)); return r;
}

__global__ void prep_g(const float* __restrict__ A, const float* __restrict__ P) {
    int i = blockIdx.x * blockDim.x + threadIdx.x;
    if (i >= Hn * NP * NP) return;
    int h = i / (NP * NP);
    int rem = i - h * NP * NP;
    int n = rem / NP;
    int m = rem - n * NP;
    float v = 0.f;
    if (n < Nn && m < Nn) v = A[n * Nn + m] * P[(h * Nn + n) * Nn + m];
    g_G[i] = v;
}

// One chunk of 2*PAIRS m-rows, fully per-warp. wb: [224][2*PAIRS] staging.
template<int PAIRS>
__device__ __forceinline__ void do_chunk(
    int m0, int b, int h, int l, bool last_h,
    const float* __restrict__ Xs, const float* __restrict__ Ks,
    const float* __restrict__ fcs, const float* __restrict__ b1s,
    const float* __restrict__ b2s, float* __restrict__ wb,
    const float* __restrict__ A, float* __restrict__ out)
{
    const int RS = 2 * PAIRS;

    // ---- feat[r][f] = sum_n G[n][r] * X[n][f]  (row-pair packed over f=2l,2l+1)
    u64 aX[PAIRS], aY[PAIRS];
    #pragma unroll
    for (int p = 0; p < PAIRS; p++) { aX[p] = 0ull; aY[p] = 0ull; }
    const float* Gh = g_G + (size_t)h * NP * NP + m0;
    #pragma unroll 4
    for (int n = 0; n < NP; n++) {
        float2 x = *(const float2*)&Xs[n * Fn + 2 * l];
        u64 xx = pack2(x.x, x.x), xy = pack2(x.y, x.y);
        const u64* gp = (const u64*)(Gh + (size_t)n * NP);
        #pragma unroll
        for (int p = 0; p < PAIRS; p++) {
            u64 g = gp[p];                        // (G[n][m0+2p], G[n][m0+2p+1])
            aX[p] = fma2(g, xx, aX[p]);
            aY[p] = fma2(g, xy, aY[p]);
        }
    }
    __syncwarp();      // prior chunk's wb reads done before restaging
    #pragma unroll
    for (int p = 0; p < PAIRS; p++) {
        *(u64*)&wb[(2 * l) * RS + 2 * p]     = aX[p];
        *(u64*)&wb[(2 * l + 1) * RS + 2 * p] = aY[p];
    }
    __syncwarp();

    // ---- dense[r][j] = sum_f feat[r][f]*K[f][j] + b1[j], j = l+32k
    u64 dP[PAIRS][7];
    #pragma unroll
    for (int k = 0; k < 7; k++) {
        float bv = b1s[l + 32 * k];
        u64 bb = pack2(bv, bv);
        #pragma unroll
        for (int p = 0; p < PAIRS; p++) dP[p][k] = bb;
    }
    #pragma unroll 2
    for (int f = 0; f < Fn; f++) {
        u64 fp[PAIRS];
        #pragma unroll
        for (int p = 0; p < PAIRS; p++) fp[p] = *(const u64*)&wb[f * RS + 2 * p];
        #pragma unroll
        for (int k = 0; k < 7; k++) {
            float kv = Ks[f * KROW + l + 32 * k];
            u64 kk = pack2(kv, kv);
            #pragma unroll
            for (int p = 0; p < PAIRS; p++) dP[p][k] = fma2(fp[p], kk, dP[p][k]);
        }
    }
    __syncwarp();      // all wb(feat) reads done before mask overwrites

    // ---- adjacency-masked softmax per row
    #pragma unroll
    for (int p = 0; p < PAIRS; p++) {
        float2 dk[7];
        #pragma unroll
        for (int k = 0; k < 7; k++) dk[k] = unpack2(dP[p][k]);
        #pragma unroll
        for (int s = 0; s < 2; s++) {
            int r = 2 * p + s, m = m0 + r;
            if (m < Nn) {
                float dv[7], av[7];
                #pragma unroll
                for (int k = 0; k < 7; k++) dv[k] = s ? dk[k].y : dk[k].x;
                #pragma unroll
                for (int k = 0; k < 7; k++) {
                    int j = l + 32 * k;
                    av[k] = (j < Nn) ? A[m * Nn + j] : 0.f;
                }
                float mx = -3.0e38f;
                #pragma unroll
                for (int k = 0; k < 7; k++) if (av[k] != 0.f) mx = fmaxf(mx, dv[k]);
                #pragma unroll
                for (int o = 16; o > 0; o >>= 1)
                    mx = fmaxf(mx, __shfl_xor_sync(0xffffffffu, mx, o));
                float ssum = 0.f;
                #pragma unroll
                for (int k = 0; k < 7; k++) {
                    float e = (av[k] != 0.f) ? __expf(dv[k] - mx) : 0.f;
                    av[k] = e; ssum += e;
                }
                #pragma unroll
                for (int o = 16; o > 0; o >>= 1)
                    ssum += __shfl_xor_sync(0xffffffffu, ssum, o);
                float inv = 1.f / ssum;
                size_t mrow = ((size_t)b * Nn + m) * OUTC + Hn * Un;
                #pragma unroll
                for (int k = 0; k < 7; k++) {
                    int j = l + 32 * k;
                    float pv = av[k] * inv;
                    wb[j * RS + r] = pv;
                    if (last_h && j < Nn) out[mrow + j] = pv;
                }
            } else {
                #pragma unroll
                for (int k = 0; k < 7; k++) wb[(l + 32 * k) * RS + r] = 0.f;
            }
        }
    }
    __syncwarp();

    // ---- node[r][f] = sum_j mask[r][j] * X[j][f]  (row-pair packed)
    u64 nX[PAIRS], nY[PAIRS];
    #pragma unroll
    for (int p = 0; p < PAIRS; p++) { nX[p] = 0ull; nY[p] = 0ull; }
    #pragma unroll 4
    for (int j = 0; j < NP; j++) {
        float2 x = *(const float2*)&Xs[j * Fn + 2 * l];
        u64 xx = pack2(x.x, x.x), xy = pack2(x.y, x.y);
        #pragma unroll
        for (int p = 0; p < PAIRS; p++) {
            u64 mm = *(const u64*)&wb[j * RS + 2 * p];
            nX[p] = fma2(mm, xx, nX[p]);
            nY[p] = fma2(mm, xy, nY[p]);
        }
    }
    __syncwarp();      // mask reads done before node staging overwrites
    #pragma unroll
    for (int p = 0; p < PAIRS; p++) {
        *(u64*)&wb[(2 * l) * RS + 2 * p]     = nX[p];
        *(u64*)&wb[(2 * l + 1) * RS + 2 * p] = nY[p];
    }
    __syncwarp();

    // ---- out[r][u] = sum_f node[r][f] * fc[f][u] + b2[u]
    u64 oX[PAIRS], oY[PAIRS];
    {
        u64 bx = pack2(b2s[2 * l], b2s[2 * l]);
        u64 by = pack2(b2s[2 * l + 1], b2s[2 * l + 1]);
        #pragma unroll
        for (int p = 0; p < PAIRS; p++) { oX[p] = bx; oY[p] = by; }
    }
    #pragma unroll 2
    for (int f = 0; f < Fn; f++) {
        float2 c = *(const float2*)&fcs[f * Un + 2 * l];
        u64 cx = pack2(c.x, c.x), cy = pack2(c.y, c.y);
        #pragma unroll
        for (int p = 0; p < PAIRS; p++) {
            u64 nn = *(const u64*)&wb[f * RS + 2 * p];
            oX[p] = fma2(nn, cx, oX[p]);
            oY[p] = fma2(nn, cy, oY[p]);
        }
    }
    #pragma unroll
    for (int p = 0; p < PAIRS; p++) {
        float2 vx = unpack2(oX[p]);   // rows (2p, 2p+1) at u = 2l
        float2 vy = unpack2(oY[p]);   // rows (2p, 2p+1) at u = 2l+1
        int m = m0 + 2 * p;
        if (m < Nn) {
            float* o = out + ((size_t)b * Nn + m) * OUTC + h * Un;
            o[2 * l] = vx.x; o[2 * l + 1] = vy.x;
        }
        if (m + 1 < Nn) {
            float* o = out + ((size_t)b * Nn + m + 1) * OUTC + h * Un;
            o[2 * l] = vx.y; o[2 * l + 1] = vy.y;
        }
    }
    __syncwarp();
}

// smem: Xs 12800 | Ks 14336 | fcs 4096 | wbuf 23296 | b1s 224 | b2s 64  = 219,264 B
#define WBUF_FLOATS (4 * (KROW * 8) + 12 * (KROW * 6))

__global__ __launch_bounds__(NT, 1)
void gc_kernel(const float* __restrict__ X, const float* __restrict__ A,
               const float* __restrict__ KER, const float* __restrict__ FC,
               const float* __restrict__ B1, const float* __restrict__ B2,
               float* __restrict__ out)
{
    extern __shared__ float sm[];
    float* Xs   = sm;                      // [NP][Fn]
    float* Ks   = Xs + NP * Fn;            // [Fn][KROW]
    float* fcs  = Ks + Fn * KROW;          // [Fn][Un]
    float* wbuf = fcs + Fn * Un;           // per-warp staging
    float* b1s  = wbuf + WBUF_FLOATS;      // [KROW]
    float* b2s  = b1s + KROW;              // [Un]

    const int b = blockIdx.x / Hn;
    const int h = blockIdx.x - b * Hn;
    const int tid = threadIdx.x;
    const int w = tid >> 5;
    const int l = tid & 31;
    const bool last_h = (h == Hn - 1);

    // ---------------- load phase ----------------
    {
        const float4* xg = (const float4*)(X + (size_t)b * (Nn * Fn));
        float4* xs4 = (float4*)Xs;
        for (int i = tid; i < NP * Fn / 4; i += NT)
            xs4[i] = (i < Nn * Fn / 4) ? xg[i] : make_float4(0.f, 0.f, 0.f, 0.f);

        const float* kg = KER + (size_t)h * (Fn * Nn);
        for (int i = tid; i < Fn * KROW; i += NT) {
            int f = i / KROW, j = i - f * KROW;
            Ks[i] = (j < Nn) ? kg[f * Nn + j] : 0.f;
        }
        const float4* fg = (const float4*)(FC + (size_t)h * (Fn * Un));
        float4* fcs4 = (float4*)fcs;
        for (int i = tid; i < Fn * Un / 4; i += NT) fcs4[i] = fg[i];

        for (int i = tid; i < KROW; i += NT) b1s[i] = (i < Nn) ? B1[h * Nn + i] : 0.f;
        if (tid < Un) b2s[tid] = B2[h * Un + tid];
    }
    __syncthreads();

    // per-warp staging base: warps 0-3 get [224][8], warps 4-15 get [224][6]
    float* wb = wbuf + (w < 4 ? w * (KROW * 8)
                              : 4 * (KROW * 8) + (w - 4) * (KROW * 6));

    // schedule: 200 rows = 4x(8-row chunk) + 28x(6-row chunk); 12% max imbalance
    if (w < 4) {
        do_chunk<4>(8 * w,          b, h, l, last_h, Xs, Ks, fcs, b1s, b2s, wb, A, out);
        do_chunk<3>(32 + 6 * w,     b, h, l, last_h, Xs, Ks, fcs, b1s, b2s, wb, A, out);
    } else {
        int c0 = 4 + 2 * (w - 4);
        do_chunk<3>(32 + 6 * c0,       b, h, l, last_h, Xs, Ks, fcs, b1s, b2s, wb, A, out);
        do_chunk<3>(32 + 6 * (c0 + 1), b, h, l, last_h, Xs, Ks, fcs, b1s, b2s, wb, A, out);
    }
}

static const size_t SMEM_BYTES =
    (size_t)(NP * Fn + Fn * KROW + Fn * Un + WBUF_FLOATS + KROW + Un) * 4;

extern "C" void kernel_launch(void* const* d_in, const int* in_sizes, int n_in,
                              void* d_out, int out_size) {
    const float* X   = (const float*)d_in[0];
    const float* A   = (const float*)d_in[1];
    const float* KER = (const float*)d_in[2];
    const float* P   = (const float*)d_in[3];
    const float* FC  = (const float*)d_in[4];
    const float* B1  = (const float*)d_in[5];
    const float* B2  = (const float*)d_in[6];
    float* out = (float*)d_out;

    cudaFuncSetAttribute(gc_kernel, cudaFuncAttributeMaxDynamicSharedMemorySize,
                         (int)SMEM_BYTES);

    prep_g<<<(Hn * NP * NP + 255) / 256, 256>>>(A, P);
    gc_kernel<<<Bn * Hn, NT, SMEM_BYTES>>>(X, A, KER, FC, B1, B2, out);
}